// round 3
// baseline (speedup 1.0000x reference)
#include <cuda_runtime.h>
#include <math.h>

// Shapes (fixed for this problem)
#define BB   512
#define MM   128
#define N3   381
#define CIN  200
#define H1   512
#define H2   512
#define FF   256

// Scratch: ping-pong activation buffers. conv1 -> buf1, conv2 buf1->buf2,
// conv3 buf2 -> buf1 (emb region).
__device__ float g_buf1[(size_t)BB * H1 * MM];   // 128 MB
__device__ float g_buf2[(size_t)BB * H2 * MM];   // 128 MB

// ---------------------------------------------------------------------------
// Fused gather + conv GEMM.
//   out[b,o,m] : m=0 -> 0, m=n+1 -> sum_{c,k} data[b,c,idx[b,3n+k]] * w[o,c,k] + bias[o]
// One block: batch b, 64-row O tile, all 128 columns. 256 threads, 4x8 reg tile.
// ---------------------------------------------------------------------------
__global__ __launch_bounds__(256) void conv_kernel(
    const float* __restrict__ data,   // [B, C, 128]
    const int*   __restrict__ idx,    // [B, 381]
    const float* __restrict__ w,      // [O, 3C]  (k fastest: w[o][c][k])
    const float* __restrict__ bias,   // [O]
    float* __restrict__ out,          // [B, O, 128]
    int C, int O)
{
    const int K  = 3 * C;
    const int b  = blockIdx.y;
    const int o0 = blockIdx.x * 64;

    __shared__ __align__(16) float As[16][68];   // [kk][o], padded
    __shared__ __align__(16) float Gs[16][128];  // [kk][n]
    __shared__ int idxs[384];

    const int t = threadIdx.x;
    // 384 entries with only 256 threads: strided load (this was the R1/R2 bug)
    for (int i = t; i < 384; i += 256)
        idxs[i] = (i < N3) ? idx[b * N3 + i] : 0;
    __syncthreads();

    const float* dB = data + (size_t)b * C * MM;
    const int ty = t >> 4;   // 0..15 (o groups of 4)
    const int tx = t & 15;   // 0..15 (n groups of 8)

    float acc[4][8];
    #pragma unroll
    for (int i = 0; i < 4; i++)
        #pragma unroll
        for (int j = 0; j < 8; j++) acc[i][j] = 0.f;

    for (int k0 = 0; k0 < K; k0 += 16) {
        // Load W tile: 64x16, coalesced along K
        #pragma unroll
        for (int i = 0; i < 4; i++) {
            int e  = i * 256 + t;
            int oo = e >> 4;
            int kk = e & 15;
            int kg = k0 + kk;
            As[kk][oo] = (kg < K) ? w[(size_t)(o0 + oo) * K + kg] : 0.f;
        }
        // Gather B tile: 16x128 from data via idx
        #pragma unroll
        for (int i = 0; i < 8; i++) {
            int e  = i * 256 + t;
            int kk = e >> 7;
            int nn = e & 127;
            int kg = k0 + kk;
            float v = 0.f;
            if (kg < K) {
                int c  = kg / 3;
                int k3 = kg - 3 * c;
                v = dB[c * MM + idxs[3 * nn + k3]];
            }
            Gs[kk][nn] = v;
        }
        __syncthreads();

        #pragma unroll
        for (int kk = 0; kk < 16; kk++) {
            float4 av = *(const float4*)&As[kk][ty * 4];
            float4 g0 = *(const float4*)&Gs[kk][tx * 8];
            float4 g1 = *(const float4*)&Gs[kk][tx * 8 + 4];
            float a[4] = {av.x, av.y, av.z, av.w};
            float g[8] = {g0.x, g0.y, g0.z, g0.w, g1.x, g1.y, g1.z, g1.w};
            #pragma unroll
            for (int i = 0; i < 4; i++)
                #pragma unroll
                for (int j = 0; j < 8; j++)
                    acc[i][j] = fmaf(a[i], g[j], acc[i][j]);
        }
        __syncthreads();
    }

    #pragma unroll
    for (int i = 0; i < 4; i++) {
        int o = o0 + ty * 4 + i;
        float bb = bias[o];
        float* op = out + ((size_t)b * O + o) * MM;
        if (tx == 0) op[0] = 0.f;               // prepended zero column
        #pragma unroll
        for (int j = 0; j < 8; j++) {
            int nn = tx * 8 + j;
            if (nn < 127) op[nn + 1] = acc[i][j] + bb;
        }
    }
}

// ---------------------------------------------------------------------------
// Per-batch LayerNorm (over O*128 elems, ddof=1, /(std+1e-5)) + ReLU, in place.
// ---------------------------------------------------------------------------
__global__ __launch_bounds__(512) void ln_relu_kernel(float* __restrict__ data, int per)
{
    const int b = blockIdx.x;
    float* p = data + (size_t)b * per;
    const int t = threadIdx.x;

    double s = 0.0, s2 = 0.0;
    for (int i = t; i < per; i += 512) {
        float v = p[i];
        s  += v;
        s2 += (double)v * v;
    }
    __shared__ double rs[512], rs2[512];
    rs[t] = s; rs2[t] = s2;
    __syncthreads();
    for (int off = 256; off > 0; off >>= 1) {
        if (t < off) { rs[t] += rs[t + off]; rs2[t] += rs2[t + off]; }
        __syncthreads();
    }
    double mean = rs[0] / per;
    double var  = (rs2[0] - (double)per * mean * mean) / (double)(per - 1);
    if (var < 0.0) var = 0.0;
    float inv = 1.f / ((float)sqrt(var) + 1e-5f);
    float mf  = (float)mean;
    for (int i = t; i < per; i += 512) {
        float v = (p[i] - mf) * inv;
        p[i] = v > 0.f ? v : 0.f;
    }
}

// ---------------------------------------------------------------------------
// Attention head + MLP, one block per batch. emb is [B, 256, 128]; et[m,f]=emb[b,f,m].
// d_out layout assumed: [ out (512) | combined (512*512) ], guarded by out_size.
// ---------------------------------------------------------------------------
__global__ __launch_bounds__(256) void head_kernel(
    const float* __restrict__ emb,
    const float* __restrict__ gw1, const float* __restrict__ gb1,
    const float* __restrict__ gw2, const float* __restrict__ gb2,
    const float* __restrict__ rw1, const float* __restrict__ rb1,
    const float* __restrict__ rw2, const float* __restrict__ rb2,
    const float* __restrict__ rw3, const float* __restrict__ rb3,
    float* __restrict__ dout, int write_comb, int write_out)
{
    const int b = blockIdx.x;
    const int t = threadIdx.x;     // 256
    const float* E = emb + (size_t)b * FF * MM;

    __shared__ __align__(16) float es[32][128];    // [f_local][m]
    __shared__ __align__(16) float gwT[32][132];   // [f_local][h], padded
    __shared__ float gates[128];
    __shared__ float red[256];
    __shared__ float attn[128];
    __shared__ __align__(16) float comb[512];
    __shared__ float h1s[128];
    __shared__ float h2s[64];

    const int m  = t >> 1;         // 0..127
    const int h0 = (t & 1) * 64;   // 0 or 64

    float acc[64];
    #pragma unroll
    for (int j = 0; j < 64; j++) acc[j] = 0.f;

    // gate1[m,h] = sum_f et[m,f]*gw1[h,f]   (f in chunks of 32)
    for (int fc = 0; fc < FF; fc += 32) {
        #pragma unroll
        for (int i = 0; i < 16; i++) {
            int e = i * 256 + t;
            es[e >> 7][e & 127] = E[(fc + (e >> 7)) * MM + (e & 127)];
        }
        #pragma unroll
        for (int i = 0; i < 16; i++) {
            int e  = i * 256 + t;
            int h  = e >> 5;
            int fl = e & 31;
            gwT[fl][h] = gw1[h * FF + fc + fl];
        }
        __syncthreads();
        #pragma unroll 2
        for (int fl = 0; fl < 32; fl++) {
            float v = es[fl][m];
            const float* gr = &gwT[fl][h0];
            #pragma unroll
            for (int j = 0; j < 64; j++) acc[j] = fmaf(v, gr[j], acc[j]);
        }
        __syncthreads();
    }

    // gate2[m] = sum_h relu(gate1+gb1) * gw2[h] + gb2
    float g2 = 0.f;
    #pragma unroll
    for (int j = 0; j < 64; j++) {
        float g = acc[j] + gb1[h0 + j];
        g2 = fmaf(fmaxf(g, 0.f), gw2[h0 + j], g2);
    }
    red[t] = g2;
    __syncthreads();
    if ((t & 1) == 0) gates[m] = red[t] + red[t + 1] + gb2[0];
    __syncthreads();

    // softmax over m (128)
    red[t] = (t < 128) ? gates[t] : -3.0e38f;
    __syncthreads();
    for (int off = 128; off > 0; off >>= 1) {
        if (t < off) red[t] = fmaxf(red[t], red[t + off]);
        __syncthreads();
    }
    float mx = red[0];
    __syncthreads();
    float ev = 0.f;
    if (t < 128) { ev = expf(gates[t] - mx); attn[t] = ev; }
    red[t] = (t < 128) ? ev : 0.f;
    __syncthreads();
    for (int off = 128; off > 0; off >>= 1) {
        if (t < off) red[t] += red[t + off];
        __syncthreads();
    }
    float inv = 1.f / red[0];
    __syncthreads();
    if (t < 128) attn[t] *= inv;
    __syncthreads();

    // pool[f] = sum_m attn[m]*et[m,f];  root[f] = et[1,f]
    {
        const int f = t;  // 0..255
        const float4* row = (const float4*)(E + f * MM);
        float pf = 0.f;
        #pragma unroll 8
        for (int q = 0; q < 32; q++) {
            float4 r = row[q];
            pf = fmaf(attn[4 * q + 0], r.x, pf);
            pf = fmaf(attn[4 * q + 1], r.y, pf);
            pf = fmaf(attn[4 * q + 2], r.z, pf);
            pf = fmaf(attn[4 * q + 3], r.w, pf);
        }
        comb[256 + f] = pf;
        comb[f]       = E[f * MM + 1];
    }
    __syncthreads();

    // combined -> d_out (after the 512-elem 'out' tensor), only if it fits
    if (write_comb) {
        dout[512 + (size_t)b * 512 + t]       = comb[t];
        dout[512 + (size_t)b * 512 + 256 + t] = comb[256 + t];
    }

    // MLP
    if (t < 128) {
        const float4* wr = (const float4*)(rw1 + t * 512);
        const float4* cb = (const float4*)comb;
        float a = rb1[t];
        #pragma unroll 8
        for (int q = 0; q < 128; q++) {
            float4 wv = wr[q];
            float4 cv = cb[q];
            a = fmaf(wv.x, cv.x, a);
            a = fmaf(wv.y, cv.y, a);
            a = fmaf(wv.z, cv.z, a);
            a = fmaf(wv.w, cv.w, a);
        }
        h1s[t] = fmaxf(a, 0.f);
    }
    __syncthreads();
    if (t < 64) {
        const float* wr = rw2 + t * 128;
        float a = rb2[t];
        #pragma unroll 4
        for (int i = 0; i < 128; i++) a = fmaf(h1s[i], wr[i], a);
        h2s[t] = fmaxf(a, 0.f);
    }
    __syncthreads();
    red[t] = (t < 64) ? h2s[t] * rw3[t] : 0.f;
    __syncthreads();
    for (int off = 32; off > 0; off >>= 1) {
        if (t < off) red[t] += red[t + off];
        __syncthreads();
    }
    if (t == 0 && write_out) dout[b] = red[0] + rb3[0];
}

// ---------------------------------------------------------------------------
extern "C" void kernel_launch(void* const* d_in, const int* in_sizes, int n_in,
                              void* d_out, int out_size)
{
    const float* trees   = (const float*)d_in[0];
    const int*   indexes = (const int*)  d_in[1];
    const float* w1  = (const float*)d_in[2];
    const float* b1  = (const float*)d_in[3];
    const float* w2  = (const float*)d_in[4];
    const float* b2  = (const float*)d_in[5];
    const float* w3  = (const float*)d_in[6];
    const float* b3  = (const float*)d_in[7];
    const float* gw1 = (const float*)d_in[8];
    const float* gb1 = (const float*)d_in[9];
    const float* gw2 = (const float*)d_in[10];
    const float* gb2 = (const float*)d_in[11];
    const float* rw1 = (const float*)d_in[12];
    const float* rb1 = (const float*)d_in[13];
    const float* rw2 = (const float*)d_in[14];
    const float* rb2 = (const float*)d_in[15];
    const float* rw3 = (const float*)d_in[16];
    const float* rb3 = (const float*)d_in[17];
    float* out = (float*)d_out;

    float *buf1, *buf2;
    cudaGetSymbolAddress((void**)&buf1, g_buf1);
    cudaGetSymbolAddress((void**)&buf2, g_buf2);

    // Does d_out have room for [out (512) | combined (512*512)]?
    const long long need_comb = 512LL + (long long)BB * 512LL;
    int write_comb = ((long long)out_size >= need_comb) ? 1 : 0;
    int write_out  = (out_size >= BB) ? 1 : 0;

    // Layer 1: conv(trees) -> buf1, LN+ReLU in place
    conv_kernel<<<dim3(H1 / 64, BB), 256>>>(trees, indexes, w1, b1, buf1, CIN, H1);
    ln_relu_kernel<<<BB, 512>>>(buf1, H1 * MM);
    // Layer 2: conv(buf1) -> buf2, LN+ReLU in place
    conv_kernel<<<dim3(H2 / 64, BB), 256>>>(buf1, indexes, w2, b2, buf2, H1, H2);
    ln_relu_kernel<<<BB, 512>>>(buf2, H2 * MM);
    // Layer 3: conv(buf2) -> buf1 (emb, [B,256,128]), no LN
    conv_kernel<<<dim3(FF / 64, BB), 256>>>(buf2, indexes, w3, b3, buf1, H2, FF);
    // Head: attention pool + MLP
    head_kernel<<<BB, 256>>>(buf1, gw1, gb1, gw2, gb2,
                             rw1, rb1, rw2, rb2, rw3, rb3, out,
                             write_comb, write_out);
}

// round 5
// speedup vs baseline: 4.4217x; 4.4217x over previous
#include <cuda_runtime.h>
#include <cuda_bf16.h>
#include <math.h>
#include <stdint.h>

// Shapes (fixed)
#define BB   512
#define MM   128
#define N3   381
#define CIN  200
#define H1   512
#define H2   512
#define FF   256
#define K1   600
#define K1P  640
#define K23  1536

// Scratch
__device__ __align__(16) float g_buf1[(size_t)BB * H1 * MM];
__device__ __align__(16) float g_buf2[(size_t)BB * H2 * MM];
__device__ __align__(16) __nv_bfloat16 g_w1_hi[H1 * K1P], g_w1_lo[H1 * K1P];
__device__ __align__(16) __nv_bfloat16 g_w2_hi[H2 * K23], g_w2_lo[H2 * K23];
__device__ __align__(16) __nv_bfloat16 g_w3_hi[FF * K23], g_w3_lo[FF * K23];
__device__ float2 g_part[BB * 4];
__device__ float2 g_stats1[BB];
__device__ float2 g_stats2[BB];

#define SW128(o) ((o) ^ (((o) >> 3) & 0x70))

__device__ __forceinline__ uint32_t smem_u32(const void* p) {
    uint32_t a;
    asm("{ .reg .u64 t; cvta.to.shared.u64 t, %1; cvt.u32.u64 %0, t; }" : "=r"(a) : "l"(p));
    return a;
}
__device__ __forceinline__ void ldmx4(uint32_t* r, uint32_t addr) {
    asm volatile("ldmatrix.sync.aligned.m8n8.x4.shared.b16 {%0,%1,%2,%3}, [%4];"
                 : "=r"(r[0]), "=r"(r[1]), "=r"(r[2]), "=r"(r[3]) : "r"(addr));
}
__device__ __forceinline__ void mma16816(float* c, const uint32_t* a, uint32_t b0, uint32_t b1) {
    asm volatile(
        "mma.sync.aligned.m16n8k16.row.col.f32.bf16.bf16.f32 "
        "{%0,%1,%2,%3},{%4,%5,%6,%7},{%8,%9},{%0,%1,%2,%3};"
        : "+f"(c[0]), "+f"(c[1]), "+f"(c[2]), "+f"(c[3])
        : "r"(a[0]), "r"(a[1]), "r"(a[2]), "r"(a[3]), "r"(b0), "r"(b1));
}

// fp32 -> bf16 hi/lo, zero-padded to KP
__global__ void wprep(const float* __restrict__ w, __nv_bfloat16* __restrict__ hi,
                      __nv_bfloat16* __restrict__ lo, int O, int K, int KP)
{
    int i = blockIdx.x * 256 + threadIdx.x;
    if (i >= O * KP) return;
    int o = i / KP, k = i - o * KP;
    float v = (k < K) ? w[o * K + k] : 0.f;
    __nv_bfloat16 h = __float2bfloat16_rn(v);
    hi[i] = h;
    lo[i] = __float2bfloat16_rn(v - __bfloat162float(h));
}

// ---------------------------------------------------------------------------
// Warp-MMA conv. D[node r (128), o_local (128)] = sum_k A[r,k] * W[o,k].
// A gathered from (optionally LN+ReLU'd) input, split bf16 hi/lo.
// Epilogue: bias add, transpose via smem, coalesced store, optional stats.
// ---------------------------------------------------------------------------
#define DYN_SMEM (69632 + 1024)

template<int O, int K, int KP, bool LN_IN, bool STATS>
__global__ __launch_bounds__(256, 1) void conv_mma(
    const float* __restrict__ data,          // [B, C, 128]
    const int*   __restrict__ idx,           // [B, 381]
    const __nv_bfloat16* __restrict__ whi,   // [O, KP]
    const __nv_bfloat16* __restrict__ wlo,
    const float* __restrict__ bias,
    const float2* __restrict__ stats_in,     // per-batch (mean, inv)
    float2* __restrict__ part_out,           // [BB * O/128]
    float* __restrict__ out,                 // [B, O, 128]
    int C)
{
    extern __shared__ char dyn_raw[];
    char* base = (char*)(((uintptr_t)dyn_raw + 1023) & ~(uintptr_t)1023);
    // stage layout (union with sD):
    const int oA_hi = 0, oA_lo = 16384, oB_hi = 32768, oB_lo = 49152;
    float* sD = (float*)base;                // [128][136] fp32, 69632B

    __shared__ int idxs[384];
    __shared__ float sbias[128];
    __shared__ float redS[8], redS2[8];

    const int b  = blockIdx.y;
    const int o0 = blockIdx.x * 128;
    const int t  = threadIdx.x;
    const int wid = t >> 5, lane = t & 31;

    for (int i = t; i < 384; i += 256) idxs[i] = (i < N3) ? idx[b * N3 + i] : 0;
    if (t < 128) sbias[t] = bias[o0 + t];
    float mean = 0.f, inv = 1.f;
    if (LN_IN) { float2 st = stats_in[b]; mean = st.x; inv = st.y; }
    __syncthreads();

    const float* dB = data + (size_t)b * C * MM;
    const uint32_t tA_hi = smem_u32(base) + oA_hi;
    const uint32_t tA_lo = smem_u32(base) + oA_lo;
    const uint32_t tB_hi = smem_u32(base) + oB_hi;
    const uint32_t tB_lo = smem_u32(base) + oB_lo;

    const int m0 = (wid & 1) * 64;   // warp M origin
    const int n0 = (wid >> 1) * 32;  // warp N origin

    float acc[4][4][4];
    #pragma unroll
    for (int i = 0; i < 4; i++)
        #pragma unroll
        for (int j = 0; j < 4; j++)
            #pragma unroll
            for (int q = 0; q < 4; q++) acc[i][j][q] = 0.f;

    const int NC = KP / 64;
    for (int ch = 0; ch < NC; ch++) {
        const int k0 = ch * 64;
        // stage W: 128 rows x 128B, hi+lo
        #pragma unroll
        for (int u = t; u < 1024; u += 256) {
            int row = u >> 3, part = u & 7;
            uint32_t d = SW128(row * 128 + part * 16);
            size_t g = (size_t)(o0 + row) * KP + k0 + part * 8;
            *(uint4*)(base + oB_hi + d) = *(const uint4*)(whi + g);
            *(uint4*)(base + oB_lo + d) = *(const uint4*)(wlo + g);
        }
        // stage gathered A: 128 rows x 64 bf16 (row 127 zero)
        #pragma unroll
        for (int e = t; e < 2048; e += 256) {
            int r = e >> 4, c4 = (e & 15) << 2;
            unsigned short hb[4], lb[4];
            #pragma unroll
            for (int u = 0; u < 4; u++) {
                int kg = k0 + c4 + u;
                float x = 0.f;
                if (r < 127 && kg < K) {
                    int c = kg / 3, k3 = kg - c * 3;
                    x = dB[c * MM + idxs[3 * r + k3]];
                    if (LN_IN) x = fmaxf((x - mean) * inv, 0.f);
                }
                __nv_bfloat16 h = __float2bfloat16_rn(x);
                __nv_bfloat16 l = __float2bfloat16_rn(x - __bfloat162float(h));
                hb[u] = __bfloat16_as_ushort(h);
                lb[u] = __bfloat16_as_ushort(l);
            }
            uint2 uh = make_uint2((uint32_t)hb[0] | ((uint32_t)hb[1] << 16),
                                  (uint32_t)hb[2] | ((uint32_t)hb[3] << 16));
            uint2 ul = make_uint2((uint32_t)lb[0] | ((uint32_t)lb[1] << 16),
                                  (uint32_t)lb[2] | ((uint32_t)lb[3] << 16));
            uint32_t d = SW128(r * 128 + (c4 << 1));
            *(uint2*)(base + oA_hi + d) = uh;
            *(uint2*)(base + oA_lo + d) = ul;
        }
        __syncthreads();

        // compute: 4 k16 steps
        #pragma unroll
        for (int ks = 0; ks < 4; ks++) {
            uint32_t ah[4][4], al[4][4];
            const int arow = lane & 15, ahalf = lane >> 4;
            #pragma unroll
            for (int mi = 0; mi < 4; mi++) {
                uint32_t off = SW128((m0 + 16 * mi + arow) * 128 + ks * 32 + ahalf * 16);
                ldmx4(ah[mi], tA_hi + off);
                ldmx4(al[mi], tA_lo + off);
            }
            uint32_t bh[2][4], bl[2][4];
            #pragma unroll
            for (int h = 0; h < 2; h++) {
                uint32_t off = SW128((n0 + lane) * 128 + ks * 32 + h * 16);
                ldmx4(bh[h], tB_hi + off);
                ldmx4(bl[h], tB_lo + off);
            }
            #pragma unroll
            for (int mi = 0; mi < 4; mi++)
                #pragma unroll
                for (int nj = 0; nj < 4; nj++) {
                    mma16816(acc[mi][nj], ah[mi], bh[0][nj], bh[1][nj]);
                    mma16816(acc[mi][nj], ah[mi], bl[0][nj], bl[1][nj]);
                    mma16816(acc[mi][nj], al[mi], bh[0][nj], bh[1][nj]);
                }
        }
        __syncthreads();
    }

    // ---- epilogue: acc -> sD[n][m] (stride 136), m = r+1, m=0 zeroed ----
    if (t < 128) sD[t * 136 + 0] = 0.f;
    #pragma unroll
    for (int mi = 0; mi < 4; mi++) {
        int r_lo = m0 + 16 * mi + (lane >> 2);
        int r_hi = r_lo + 8;
        #pragma unroll
        for (int nj = 0; nj < 4; nj++) {
            int n = n0 + 8 * nj + 2 * (lane & 3);
            float bb0 = sbias[n], bb1 = sbias[n + 1];
            sD[n * 136 + r_lo + 1]       = acc[mi][nj][0] + bb0;
            sD[(n + 1) * 136 + r_lo + 1] = acc[mi][nj][1] + bb1;
            if (r_hi < 127) {
                sD[n * 136 + r_hi + 1]       = acc[mi][nj][2] + bb0;
                sD[(n + 1) * 136 + r_hi + 1] = acc[mi][nj][3] + bb1;
            }
        }
    }
    __syncthreads();

    if (STATS) {
        int o = t >> 1, mh = (t & 1) * 64;
        float s = 0.f, s2 = 0.f;
        #pragma unroll
        for (int i = 0; i < 64; i += 4) {
            float4 x = *(float4*)&sD[o * 136 + mh + i];
            s  += x.x + x.y + x.z + x.w;
            s2 += x.x * x.x + x.y * x.y + x.z * x.z + x.w * x.w;
        }
        #pragma unroll
        for (int off = 16; off; off >>= 1) {
            s  += __shfl_xor_sync(0xFFFFFFFFu, s,  off);
            s2 += __shfl_xor_sync(0xFFFFFFFFu, s2, off);
        }
        if (lane == 0) { redS[wid] = s; redS2[wid] = s2; }
        __syncthreads();
        if (t == 0) {
            float S = 0.f, S2 = 0.f;
            #pragma unroll
            for (int i = 0; i < 8; i++) { S += redS[i]; S2 += redS2[i]; }
            part_out[b * (O / 128) + blockIdx.x] = make_float2(S, S2);
        }
    }

    // coalesced store
    float* outB = out + ((size_t)b * O + o0) * MM;
    {
        int o = t >> 1, h = t & 1;
        #pragma unroll
        for (int i = 0; i < 16; i++) {
            int m = h * 4 + 8 * i;
            *(float4*)&outB[o * MM + m] = *(float4*)&sD[o * 136 + m];
        }
    }
}

__global__ void finalize_stats(const float2* __restrict__ part, int nOC,
                               float2* __restrict__ stats, float cnt)
{
    int b = blockIdx.x * blockDim.x + threadIdx.x;
    if (b >= BB) return;
    float S = 0.f, S2 = 0.f;
    for (int i = 0; i < nOC; i++) { float2 p = part[b * nOC + i]; S += p.x; S2 += p.y; }
    double mean = (double)S / (double)cnt;
    double var  = ((double)S2 - (double)S * (double)S / (double)cnt) / ((double)cnt - 1.0);
    if (var < 0.0) var = 0.0;
    stats[b] = make_float2((float)mean, 1.f / ((float)sqrt(var) + 1e-5f));
}

// ---------------------------------------------------------------------------
// Attention head + MLP (unchanged, known correct)
// ---------------------------------------------------------------------------
__global__ __launch_bounds__(256) void head_kernel(
    const float* __restrict__ emb,
    const float* __restrict__ gw1, const float* __restrict__ gb1,
    const float* __restrict__ gw2, const float* __restrict__ gb2,
    const float* __restrict__ rw1, const float* __restrict__ rb1,
    const float* __restrict__ rw2, const float* __restrict__ rb2,
    const float* __restrict__ rw3, const float* __restrict__ rb3,
    float* __restrict__ dout, int write_comb, int write_out)
{
    const int b = blockIdx.x;
    const int t = threadIdx.x;
    const float* E = emb + (size_t)b * FF * MM;

    __shared__ __align__(16) float es[32][128];
    __shared__ __align__(16) float gwT[32][132];
    __shared__ float gates[128];
    __shared__ float red[256];
    __shared__ float attn[128];
    __shared__ __align__(16) float comb[512];
    __shared__ float h1s[128];
    __shared__ float h2s[64];

    const int m  = t >> 1;
    const int h0 = (t & 1) * 64;

    float acc[64];
    #pragma unroll
    for (int j = 0; j < 64; j++) acc[j] = 0.f;

    for (int fc = 0; fc < FF; fc += 32) {
        #pragma unroll
        for (int i = 0; i < 16; i++) {
            int e = i * 256 + t;
            es[e >> 7][e & 127] = E[(fc + (e >> 7)) * MM + (e & 127)];
        }
        #pragma unroll
        for (int i = 0; i < 16; i++) {
            int e = i * 256 + t;
            gwT[e & 31][e >> 5] = gw1[(e >> 5) * FF + fc + (e & 31)];
        }
        __syncthreads();
        #pragma unroll 2
        for (int fl = 0; fl < 32; fl++) {
            float v = es[fl][m];
            const float* gr = &gwT[fl][h0];
            #pragma unroll
            for (int j = 0; j < 64; j++) acc[j] = fmaf(v, gr[j], acc[j]);
        }
        __syncthreads();
    }

    float g2 = 0.f;
    #pragma unroll
    for (int j = 0; j < 64; j++) {
        float g = acc[j] + gb1[h0 + j];
        g2 = fmaf(fmaxf(g, 0.f), gw2[h0 + j], g2);
    }
    red[t] = g2;
    __syncthreads();
    if ((t & 1) == 0) gates[m] = red[t] + red[t + 1] + gb2[0];
    __syncthreads();

    red[t] = (t < 128) ? gates[t] : -3.0e38f;
    __syncthreads();
    for (int off = 128; off > 0; off >>= 1) {
        if (t < off) red[t] = fmaxf(red[t], red[t + off]);
        __syncthreads();
    }
    float mx = red[0];
    __syncthreads();
    float ev = 0.f;
    if (t < 128) { ev = expf(gates[t] - mx); attn[t] = ev; }
    red[t] = (t < 128) ? ev : 0.f;
    __syncthreads();
    for (int off = 128; off > 0; off >>= 1) {
        if (t < off) red[t] += red[t + off];
        __syncthreads();
    }
    float sinv = 1.f / red[0];
    __syncthreads();
    if (t < 128) attn[t] *= sinv;
    __syncthreads();

    {
        const int f = t;
        const float4* row = (const float4*)(E + f * MM);
        float pf = 0.f;
        #pragma unroll 8
        for (int q = 0; q < 32; q++) {
            float4 rr = row[q];
            pf = fmaf(attn[4 * q + 0], rr.x, pf);
            pf = fmaf(attn[4 * q + 1], rr.y, pf);
            pf = fmaf(attn[4 * q + 2], rr.z, pf);
            pf = fmaf(attn[4 * q + 3], rr.w, pf);
        }
        comb[256 + f] = pf;
        comb[f]       = E[f * MM + 1];
    }
    __syncthreads();

    if (write_comb) {
        dout[512 + (size_t)b * 512 + t]       = comb[t];
        dout[512 + (size_t)b * 512 + 256 + t] = comb[256 + t];
    }

    if (t < 128) {
        const float4* wr = (const float4*)(rw1 + t * 512);
        const float4* cb = (const float4*)comb;
        float a = rb1[t];
        #pragma unroll 8
        for (int q = 0; q < 128; q++) {
            float4 wv = wr[q];
            float4 cv = cb[q];
            a = fmaf(wv.x, cv.x, a);
            a = fmaf(wv.y, cv.y, a);
            a = fmaf(wv.z, cv.z, a);
            a = fmaf(wv.w, cv.w, a);
        }
        h1s[t] = fmaxf(a, 0.f);
    }
    __syncthreads();
    if (t < 64) {
        const float* wr = rw2 + t * 128;
        float a = rb2[t];
        #pragma unroll 4
        for (int i = 0; i < 128; i++) a = fmaf(h1s[i], wr[i], a);
        h2s[t] = fmaxf(a, 0.f);
    }
    __syncthreads();
    red[t] = (t < 64) ? h2s[t] * rw3[t] : 0.f;
    __syncthreads();
    for (int off = 32; off > 0; off >>= 1) {
        if (t < off) red[t] += red[t + off];
        __syncthreads();
    }
    if (t == 0 && write_out) dout[b] = red[0] + rb3[0];
}

// ---------------------------------------------------------------------------
extern "C" void kernel_launch(void* const* d_in, const int* in_sizes, int n_in,
                              void* d_out, int out_size)
{
    const float* trees   = (const float*)d_in[0];
    const int*   indexes = (const int*)  d_in[1];
    const float* w1  = (const float*)d_in[2];
    const float* b1  = (const float*)d_in[3];
    const float* w2  = (const float*)d_in[4];
    const float* b2  = (const float*)d_in[5];
    const float* w3  = (const float*)d_in[6];
    const float* b3  = (const float*)d_in[7];
    const float* gw1 = (const float*)d_in[8];
    const float* gb1 = (const float*)d_in[9];
    const float* gw2 = (const float*)d_in[10];
    const float* gb2 = (const float*)d_in[11];
    const float* rw1 = (const float*)d_in[12];
    const float* rb1 = (const float*)d_in[13];
    const float* rw2 = (const float*)d_in[14];
    const float* rb2 = (const float*)d_in[15];
    const float* rw3 = (const float*)d_in[16];
    const float* rb3 = (const float*)d_in[17];
    float* out = (float*)d_out;

    float *buf1, *buf2;
    __nv_bfloat16 *w1h, *w1l, *w2h, *w2l, *w3h, *w3l;
    float2 *part, *st1, *st2;
    cudaGetSymbolAddress((void**)&buf1, g_buf1);
    cudaGetSymbolAddress((void**)&buf2, g_buf2);
    cudaGetSymbolAddress((void**)&w1h, g_w1_hi);
    cudaGetSymbolAddress((void**)&w1l, g_w1_lo);
    cudaGetSymbolAddress((void**)&w2h, g_w2_hi);
    cudaGetSymbolAddress((void**)&w2l, g_w2_lo);
    cudaGetSymbolAddress((void**)&w3h, g_w3_hi);
    cudaGetSymbolAddress((void**)&w3l, g_w3_lo);
    cudaGetSymbolAddress((void**)&part, g_part);
    cudaGetSymbolAddress((void**)&st1, g_stats1);
    cudaGetSymbolAddress((void**)&st2, g_stats2);

    cudaFuncSetAttribute(conv_mma<H1, K1, K1P, false, true>,
                         cudaFuncAttributeMaxDynamicSharedMemorySize, DYN_SMEM);
    cudaFuncSetAttribute(conv_mma<H2, K23, K23, true, true>,
                         cudaFuncAttributeMaxDynamicSharedMemorySize, DYN_SMEM);
    cudaFuncSetAttribute(conv_mma<FF, K23, K23, true, false>,
                         cudaFuncAttributeMaxDynamicSharedMemorySize, DYN_SMEM);

    const long long need_comb = 512LL + (long long)BB * 512LL;
    int write_comb = ((long long)out_size >= need_comb) ? 1 : 0;
    int write_out  = (out_size >= BB) ? 1 : 0;

    wprep<<<(H1 * K1P + 255) / 256, 256>>>(w1, w1h, w1l, H1, K1, K1P);
    wprep<<<(H2 * K23 + 255) / 256, 256>>>(w2, w2h, w2l, H2, K23, K23);
    wprep<<<(FF * K23 + 255) / 256, 256>>>(w3, w3h, w3l, FF, K23, K23);

    conv_mma<H1, K1, K1P, false, true><<<dim3(H1 / 128, BB), 256, DYN_SMEM>>>(
        trees, indexes, w1h, w1l, b1, nullptr, part, buf1, CIN);
    finalize_stats<<<(BB + 127) / 128, 128>>>(part, H1 / 128, st1, (float)(H1 * MM));

    conv_mma<H2, K23, K23, true, true><<<dim3(H2 / 128, BB), 256, DYN_SMEM>>>(
        buf1, indexes, w2h, w2l, b2, st1, part, buf2, H1);
    finalize_stats<<<(BB + 127) / 128, 128>>>(part, H2 / 128, st2, (float)(H2 * MM));

    conv_mma<FF, K23, K23, true, false><<<dim3(FF / 128, BB), 256, DYN_SMEM>>>(
        buf2, indexes, w3h, w3l, b3, st2, nullptr, buf1, H2);

    head_kernel<<<BB, 256>>>(buf1, gw1, gb1, gw2, gb2,
                             rw1, rb1, rw2, rb2, rw3, rb3, out,
                             write_comb, write_out);
}

// round 8
// speedup vs baseline: 5.4370x; 1.2296x over previous
#include <cuda_runtime.h>
#include <cuda_bf16.h>
#include <math.h>
#include <stdint.h>

// Shapes (fixed)
#define BB   512
#define MM   128
#define N3   381
#define CIN  200
#define CP1  256        // padded input channels, layer 1
#define H1   512
#define H2   512
#define FF   256

// Activations, node-major [B][128][C]
__device__ __align__(16) float g_bufT[(size_t)BB * MM * CP1];  // transposed trees / emb
__device__ __align__(16) float g_buf1[(size_t)BB * MM * H1];
__device__ __align__(16) float g_buf2[(size_t)BB * MM * H2];
// Weights, k' = k3*Cp + c order, bf16 hi/lo
__device__ __align__(16) __nv_bfloat16 g_w1_hi[H1 * 3 * CP1], g_w1_lo[H1 * 3 * CP1];
__device__ __align__(16) __nv_bfloat16 g_w2_hi[H2 * 3 * H1],  g_w2_lo[H2 * 3 * H1];
__device__ __align__(16) __nv_bfloat16 g_w3_hi[FF * 3 * H2],  g_w3_lo[FF * 3 * H2];
__device__ float2 g_part[BB * 4];
__device__ float2 g_stats1[BB];
__device__ float2 g_stats2[BB];

#define SW128(o) ((o) ^ (((o) >> 3) & 0x70))

__device__ __forceinline__ uint32_t smem_u32(const void* p) {
    uint32_t a;
    asm("{ .reg .u64 t; cvta.to.shared.u64 t, %1; cvt.u32.u64 %0, t; }" : "=r"(a) : "l"(p));
    return a;
}
__device__ __forceinline__ void ldmx4(uint32_t* r, uint32_t addr) {
    asm volatile("ldmatrix.sync.aligned.m8n8.x4.shared.b16 {%0,%1,%2,%3}, [%4];"
                 : "=r"(r[0]), "=r"(r[1]), "=r"(r[2]), "=r"(r[3]) : "r"(addr));
}
__device__ __forceinline__ void mma16816(float* c, const uint32_t* a, uint32_t b0, uint32_t b1) {
    asm volatile(
        "mma.sync.aligned.m16n8k16.row.col.f32.bf16.bf16.f32 "
        "{%0,%1,%2,%3},{%4,%5,%6,%7},{%8,%9},{%0,%1,%2,%3};"
        : "+f"(c[0]), "+f"(c[1]), "+f"(c[2]), "+f"(c[3])
        : "r"(a[0]), "r"(a[1]), "r"(a[2]), "r"(a[3]), "r"(b0), "r"(b1));
}

// ---------------------------------------------------------------------------
// trees [B][CIN][128] -> bufT [B][128][CP1] (pad c>=CIN with 0)
// ---------------------------------------------------------------------------
__global__ __launch_bounds__(256) void transpose_trees(
    const float* __restrict__ in, float* __restrict__ outp)
{
    __shared__ float tile[32][33];
    const int b = blockIdx.z;
    const int c0 = blockIdx.x * 32, m0 = blockIdx.y * 32;
    const int tx = threadIdx.x & 31, ty = threadIdx.x >> 5;   // 32 x 8
    const float* ib = in + (size_t)b * CIN * MM;
    #pragma unroll
    for (int i = 0; i < 4; i++) {
        int c = c0 + ty + i * 8;
        tile[ty + i * 8][tx] = (c < CIN) ? ib[c * MM + m0 + tx] : 0.f;
    }
    __syncthreads();
    float* ob = outp + (size_t)b * MM * CP1;
    #pragma unroll
    for (int i = 0; i < 4; i++) {
        int m = m0 + ty + i * 8;
        ob[m * CP1 + c0 + tx] = tile[tx][ty + i * 8];
    }
}

// ---------------------------------------------------------------------------
// W[o][c*3+k3] -> hi/lo bf16 at [o][k3*Cp + c], zero-pad c>=C
// ---------------------------------------------------------------------------
__global__ void wprep(const float* __restrict__ w, __nv_bfloat16* __restrict__ hi,
                      __nv_bfloat16* __restrict__ lo, int O, int C, int Cp)
{
    int i = blockIdx.x * 256 + threadIdx.x;
    int KT = 3 * Cp;
    if (i >= O * KT) return;
    int o = i / KT, kp = i - o * KT;
    int k3 = kp / Cp, c = kp - k3 * Cp;
    float v = (c < C) ? w[o * C * 3 + c * 3 + k3] : 0.f;
    __nv_bfloat16 h = __float2bfloat16_rn(v);
    hi[i] = h;
    lo[i] = __float2bfloat16_rn(v - __bfloat162float(h));
}

// ---------------------------------------------------------------------------
// Node-major warp-MMA conv, 2-stage pipelined staging.
//   D[m, o_local] = sum_{k3,c} X[idx[3(m-1)+k3], c] * W[o][k3*Cp+c]
// X node-major [B][128][Cp]; out node-major [B][128][O] (row 0 = zeros).
// ---------------------------------------------------------------------------
#define STG   65536
#define DYN_SMEM (2 * STG + 128 * 132 * 4)

template<int O, int Cp, bool LN_IN, bool STATS>
__global__ __launch_bounds__(256, 1) void conv_mma(
    const float* __restrict__ X,             // [B][128][Cp]
    const int*   __restrict__ idx,           // [B][381]
    const __nv_bfloat16* __restrict__ whi,   // [O][3*Cp]
    const __nv_bfloat16* __restrict__ wlo,
    const float* __restrict__ bias,
    const float2* __restrict__ stats_in,
    float2* __restrict__ part_out,
    float* __restrict__ out)                 // [B][128][O]
{
    const int KT = 3 * Cp;
    const int NCH = Cp / 64;                 // chunks per k3
    const int NC = 3 * NCH;

    extern __shared__ char dyn_raw[];
    char* base = (char*)dyn_raw;
    float* sD = (float*)(base + 2 * STG);    // [128][132]

    __shared__ int idxs[384];
    __shared__ float sbias[128];
    __shared__ float redS[8], redS2[8];

    const int b  = blockIdx.y;
    const int o0 = blockIdx.x * 128;
    const int t  = threadIdx.x;
    const int wid = t >> 5, lane = t & 31;

    for (int i = t; i < 384; i += 256) idxs[i] = (i < N3) ? idx[b * N3 + i] : 0;
    if (t < 128) sbias[t] = bias[o0 + t];
    float mean = 0.f, inv = 1.f;
    if (LN_IN) { float2 st = stats_in[b]; mean = st.x; inv = st.y; }
    __syncthreads();

    const float* Xb = X + (size_t)b * MM * Cp;
    const uint32_t sbase = smem_u32(base);

    // A-stage per-thread geometry: warp rows [wid*16, wid*16+16)
    const int ar_base = wid * 16 + (lane >> 4);   // + 2*i
    const int acp = lane & 15;

    float4 apf[8];
    uint4  bhpf[4], blpf[4];

    auto load_pf = [&](int ch) {
        const int k3 = ch / NCH, c0 = (ch - k3 * NCH) * 64;
        #pragma unroll
        for (int i = 0; i < 8; i++) {
            int r = ar_base + 2 * i;
            int m = (r < 127) ? idxs[3 * r + k3] : 0;
            apf[i] = *(const float4*)(Xb + (size_t)m * Cp + c0 + acp * 4);
        }
        #pragma unroll
        for (int i = 0; i < 4; i++) {
            int e = i * 256 + t;              // 0..1023
            int row = e >> 3, part = e & 7;
            size_t g = (size_t)(o0 + row) * KT + k3 * Cp + c0 + part * 8;
            bhpf[i] = *(const uint4*)(whi + g);
            blpf[i] = *(const uint4*)(wlo + g);
        }
    };
    auto store_pf = [&](int s) {
        char* st = base + s * STG;
        #pragma unroll
        for (int i = 0; i < 4; i++) {
            int e = i * 256 + t;
            int row = e >> 3, part = e & 7;
            uint32_t d = SW128(row * 128 + part * 16);
            *(uint4*)(st + 32768 + d) = bhpf[i];
            *(uint4*)(st + 49152 + d) = blpf[i];
        }
        #pragma unroll
        for (int i = 0; i < 8; i++) {
            int r = ar_base + 2 * i;
            float x4[4] = {apf[i].x, apf[i].y, apf[i].z, apf[i].w};
            unsigned short hb[4], lb[4];
            #pragma unroll
            for (int u = 0; u < 4; u++) {
                float x = x4[u];
                if (LN_IN) x = fmaxf((x - mean) * inv, 0.f);
                if (r >= 127) x = 0.f;
                __nv_bfloat16 h = __float2bfloat16_rn(x);
                __nv_bfloat16 l = __float2bfloat16_rn(x - __bfloat162float(h));
                hb[u] = __bfloat16_as_ushort(h);
                lb[u] = __bfloat16_as_ushort(l);
            }
            uint2 uh = make_uint2((uint32_t)hb[0] | ((uint32_t)hb[1] << 16),
                                  (uint32_t)hb[2] | ((uint32_t)hb[3] << 16));
            uint2 ul = make_uint2((uint32_t)lb[0] | ((uint32_t)lb[1] << 16),
                                  (uint32_t)lb[2] | ((uint32_t)lb[3] << 16));
            // 4 bf16 = 8 bytes per thread -> byte offset acp*8 (acp*16 was the R7 bug)
            uint32_t d = SW128(r * 128 + acp * 8);
            *(uint2*)(st + 0     + d) = uh;
            *(uint2*)(st + 16384 + d) = ul;
        }
    };

    const int m0 = (wid & 1) * 64;
    const int n0 = (wid >> 1) * 32;

    float acc[4][4][4];
    #pragma unroll
    for (int i = 0; i < 4; i++)
        #pragma unroll
        for (int j = 0; j < 4; j++)
            #pragma unroll
            for (int q = 0; q < 4; q++) acc[i][j][q] = 0.f;

    load_pf(0);
    store_pf(0);
    __syncthreads();

    for (int ch = 0; ch < NC; ch++) {
        const int s = ch & 1;
        if (ch + 1 < NC) load_pf(ch + 1);

        const uint32_t tA_hi = sbase + s * STG;
        const uint32_t tA_lo = tA_hi + 16384;
        const uint32_t tB_hi = tA_hi + 32768;
        const uint32_t tB_lo = tA_hi + 49152;
        #pragma unroll
        for (int ks = 0; ks < 4; ks++) {
            uint32_t ah[4][4], al[4][4];
            const int arow = lane & 15, ahalf = lane >> 4;
            #pragma unroll
            for (int mi = 0; mi < 4; mi++) {
                uint32_t off = SW128((m0 + 16 * mi + arow) * 128 + ks * 32 + ahalf * 16);
                ldmx4(ah[mi], tA_hi + off);
                ldmx4(al[mi], tA_lo + off);
            }
            uint32_t bh[2][4], bl[2][4];
            #pragma unroll
            for (int h = 0; h < 2; h++) {
                uint32_t off = SW128((n0 + lane) * 128 + ks * 32 + h * 16);
                ldmx4(bh[h], tB_hi + off);
                ldmx4(bl[h], tB_lo + off);
            }
            #pragma unroll
            for (int mi = 0; mi < 4; mi++)
                #pragma unroll
                for (int nj = 0; nj < 4; nj++) {
                    mma16816(acc[mi][nj], ah[mi], bh[0][nj], bh[1][nj]);
                    mma16816(acc[mi][nj], ah[mi], bl[0][nj], bl[1][nj]);
                    mma16816(acc[mi][nj], al[mi], bh[0][nj], bh[1][nj]);
                }
        }
        if (ch + 1 < NC) store_pf(s ^ 1);
        __syncthreads();
    }

    // ---- epilogue: acc -> sD[m][o_local] (m = r+1, row 0 zeroed) ----
    if (t < 128) sD[0 * 132 + t] = 0.f;
    #pragma unroll
    for (int mi = 0; mi < 4; mi++) {
        int r_lo = m0 + 16 * mi + (lane >> 2);
        int r_hi = r_lo + 8;
        #pragma unroll
        for (int nj = 0; nj < 4; nj++) {
            int n = n0 + 8 * nj + 2 * (lane & 3);
            float bb0 = sbias[n], bb1 = sbias[n + 1];
            sD[(r_lo + 1) * 132 + n]     = acc[mi][nj][0] + bb0;
            sD[(r_lo + 1) * 132 + n + 1] = acc[mi][nj][1] + bb1;
            if (r_hi < 127) {
                sD[(r_hi + 1) * 132 + n]     = acc[mi][nj][2] + bb0;
                sD[(r_hi + 1) * 132 + n + 1] = acc[mi][nj][3] + bb1;
            }
        }
    }
    __syncthreads();

    if (STATS) {
        int m = t >> 1, half = (t & 1) * 64;
        float s = 0.f, s2 = 0.f;
        #pragma unroll
        for (int i = 0; i < 64; i += 4) {
            float4 x = *(float4*)&sD[m * 132 + half + i];
            s  += x.x + x.y + x.z + x.w;
            s2 += x.x * x.x + x.y * x.y + x.z * x.z + x.w * x.w;
        }
        #pragma unroll
        for (int off = 16; off; off >>= 1) {
            s  += __shfl_xor_sync(0xFFFFFFFFu, s,  off);
            s2 += __shfl_xor_sync(0xFFFFFFFFu, s2, off);
        }
        if (lane == 0) { redS[wid] = s; redS2[wid] = s2; }
        __syncthreads();
        if (t == 0) {
            float S = 0.f, S2 = 0.f;
            #pragma unroll
            for (int i = 0; i < 8; i++) { S += redS[i]; S2 += redS2[i]; }
            part_out[b * (O / 128) + blockIdx.x] = make_float2(S, S2);
        }
    }

    // coalesced node-major store: out[b][m][o0 + ...]
    {
        float* outB = out + (size_t)b * MM * O + o0;
        int m = t >> 1, half = (t & 1) * 64;
        #pragma unroll
        for (int i = 0; i < 16; i++)
            *(float4*)&outB[(size_t)m * O + half + i * 4] = *(float4*)&sD[m * 132 + half + i * 4];
    }
}

__global__ void finalize_stats(const float2* __restrict__ part, int nOC,
                               float2* __restrict__ stats, float cnt)
{
    int b = blockIdx.x * blockDim.x + threadIdx.x;
    if (b >= BB) return;
    float S = 0.f, S2 = 0.f;
    for (int i = 0; i < nOC; i++) { float2 p = part[b * nOC + i]; S += p.x; S2 += p.y; }
    double mean = (double)S / (double)cnt;
    double var  = ((double)S2 - (double)S * (double)S / (double)cnt) / ((double)cnt - 1.0);
    if (var < 0.0) var = 0.0;
    stats[b] = make_float2((float)mean, 1.f / ((float)sqrt(var) + 1e-5f));
}

// ---------------------------------------------------------------------------
// Attention head + MLP, emb node-major [B][128][256] (= et directly)
// ---------------------------------------------------------------------------
__global__ __launch_bounds__(256) void head_kernel(
    const float* __restrict__ emb,
    const float* __restrict__ gw1, const float* __restrict__ gb1,
    const float* __restrict__ gw2, const float* __restrict__ gb2,
    const float* __restrict__ rw1, const float* __restrict__ rb1,
    const float* __restrict__ rw2, const float* __restrict__ rb2,
    const float* __restrict__ rw3, const float* __restrict__ rb3,
    float* __restrict__ dout, int write_comb, int write_out)
{
    const int b = blockIdx.x;
    const int t = threadIdx.x;
    const float* E = emb + (size_t)b * MM * FF;   // E[m*256 + f]

    __shared__ __align__(16) float es[128][33];   // [m][fl]
    __shared__ __align__(16) float gwT[32][132];
    __shared__ float gates[128];
    __shared__ float red[256];
    __shared__ float attn[128];
    __shared__ __align__(16) float comb[512];
    __shared__ float h1s[128];
    __shared__ float h2s[64];

    const int m  = t >> 1;
    const int h0 = (t & 1) * 64;

    float acc[64];
    #pragma unroll
    for (int j = 0; j < 64; j++) acc[j] = 0.f;

    for (int fc = 0; fc < FF; fc += 32) {
        #pragma unroll
        for (int i = 0; i < 16; i++) {
            int e = i * 256 + t;
            es[e >> 5][e & 31] = E[(e >> 5) * FF + fc + (e & 31)];
        }
        #pragma unroll
        for (int i = 0; i < 16; i++) {
            int e = i * 256 + t;
            gwT[e & 31][e >> 5] = gw1[(e >> 5) * FF + fc + (e & 31)];
        }
        __syncthreads();
        #pragma unroll 2
        for (int fl = 0; fl < 32; fl++) {
            float v = es[m][fl];
            const float* gr = &gwT[fl][h0];
            #pragma unroll
            for (int j = 0; j < 64; j++) acc[j] = fmaf(v, gr[j], acc[j]);
        }
        __syncthreads();
    }

    float g2 = 0.f;
    #pragma unroll
    for (int j = 0; j < 64; j++) {
        float g = acc[j] + gb1[h0 + j];
        g2 = fmaf(fmaxf(g, 0.f), gw2[h0 + j], g2);
    }
    red[t] = g2;
    __syncthreads();
    if ((t & 1) == 0) gates[m] = red[t] + red[t + 1] + gb2[0];
    __syncthreads();

    red[t] = (t < 128) ? gates[t] : -3.0e38f;
    __syncthreads();
    for (int off = 128; off > 0; off >>= 1) {
        if (t < off) red[t] = fmaxf(red[t], red[t + off]);
        __syncthreads();
    }
    float mx = red[0];
    __syncthreads();
    float ev = 0.f;
    if (t < 128) { ev = expf(gates[t] - mx); attn[t] = ev; }
    red[t] = (t < 128) ? ev : 0.f;
    __syncthreads();
    for (int off = 128; off > 0; off >>= 1) {
        if (t < off) red[t] += red[t + off];
        __syncthreads();
    }
    float sinv = 1.f / red[0];
    __syncthreads();
    if (t < 128) attn[t] *= sinv;
    __syncthreads();

    // pool[f] = sum_m attn[m] * E[m][f];  root[f] = E[1][f]
    {
        const int f = t;
        float pf = 0.f;
        #pragma unroll 4
        for (int mi = 0; mi < 128; mi++)
            pf = fmaf(attn[mi], E[mi * FF + f], pf);
        comb[256 + f] = pf;
        comb[f]       = E[FF + f];
    }
    __syncthreads();

    if (write_comb) {
        dout[512 + (size_t)b * 512 + t]       = comb[t];
        dout[512 + (size_t)b * 512 + 256 + t] = comb[256 + t];
    }

    if (t < 128) {
        const float4* wr = (const float4*)(rw1 + t * 512);
        const float4* cb = (const float4*)comb;
        float a = rb1[t];
        #pragma unroll 8
        for (int q = 0; q < 128; q++) {
            float4 wv = wr[q];
            float4 cv = cb[q];
            a = fmaf(wv.x, cv.x, a);
            a = fmaf(wv.y, cv.y, a);
            a = fmaf(wv.z, cv.z, a);
            a = fmaf(wv.w, cv.w, a);
        }
        h1s[t] = fmaxf(a, 0.f);
    }
    __syncthreads();
    if (t < 64) {
        const float* wr = rw2 + t * 128;
        float a = rb2[t];
        #pragma unroll 4
        for (int i = 0; i < 128; i++) a = fmaf(h1s[i], wr[i], a);
        h2s[t] = fmaxf(a, 0.f);
    }
    __syncthreads();
    red[t] = (t < 64) ? h2s[t] * rw3[t] : 0.f;
    __syncthreads();
    for (int off = 32; off > 0; off >>= 1) {
        if (t < off) red[t] += red[t + off];
        __syncthreads();
    }
    if (t == 0 && write_out) dout[b] = red[0] + rb3[0];
}

// ---------------------------------------------------------------------------
extern "C" void kernel_launch(void* const* d_in, const int* in_sizes, int n_in,
                              void* d_out, int out_size)
{
    const float* trees   = (const float*)d_in[0];
    const int*   indexes = (const int*)  d_in[1];
    const float* w1  = (const float*)d_in[2];
    const float* b1  = (const float*)d_in[3];
    const float* w2  = (const float*)d_in[4];
    const float* b2  = (const float*)d_in[5];
    const float* w3  = (const float*)d_in[6];
    const float* b3  = (const float*)d_in[7];
    const float* gw1 = (const float*)d_in[8];
    const float* gb1 = (const float*)d_in[9];
    const float* gw2 = (const float*)d_in[10];
    const float* gb2 = (const float*)d_in[11];
    const float* rw1 = (const float*)d_in[12];
    const float* rb1 = (const float*)d_in[13];
    const float* rw2 = (const float*)d_in[14];
    const float* rb2 = (const float*)d_in[15];
    const float* rw3 = (const float*)d_in[16];
    const float* rb3 = (const float*)d_in[17];
    float* out = (float*)d_out;

    float *bufT, *buf1, *buf2;
    __nv_bfloat16 *w1h, *w1l, *w2h, *w2l, *w3h, *w3l;
    float2 *part, *st1, *st2;
    cudaGetSymbolAddress((void**)&bufT, g_bufT);
    cudaGetSymbolAddress((void**)&buf1, g_buf1);
    cudaGetSymbolAddress((void**)&buf2, g_buf2);
    cudaGetSymbolAddress((void**)&w1h, g_w1_hi);
    cudaGetSymbolAddress((void**)&w1l, g_w1_lo);
    cudaGetSymbolAddress((void**)&w2h, g_w2_hi);
    cudaGetSymbolAddress((void**)&w2l, g_w2_lo);
    cudaGetSymbolAddress((void**)&w3h, g_w3_hi);
    cudaGetSymbolAddress((void**)&w3l, g_w3_lo);
    cudaGetSymbolAddress((void**)&part, g_part);
    cudaGetSymbolAddress((void**)&st1, g_stats1);
    cudaGetSymbolAddress((void**)&st2, g_stats2);

    cudaFuncSetAttribute(conv_mma<H1, CP1, false, true>,
                         cudaFuncAttributeMaxDynamicSharedMemorySize, DYN_SMEM);
    cudaFuncSetAttribute(conv_mma<H2, H1, true, true>,
                         cudaFuncAttributeMaxDynamicSharedMemorySize, DYN_SMEM);
    cudaFuncSetAttribute(conv_mma<FF, H2, true, false>,
                         cudaFuncAttributeMaxDynamicSharedMemorySize, DYN_SMEM);

    const long long need_comb = 512LL + (long long)BB * 512LL;
    int write_comb = ((long long)out_size >= need_comb) ? 1 : 0;
    int write_out  = (out_size >= BB) ? 1 : 0;

    transpose_trees<<<dim3(CP1 / 32, MM / 32, BB), 256>>>(trees, bufT);
    wprep<<<(H1 * 3 * CP1 + 255) / 256, 256>>>(w1, w1h, w1l, H1, CIN, CP1);
    wprep<<<(H2 * 3 * H1 + 255) / 256, 256>>>(w2, w2h, w2l, H2, H1, H1);
    wprep<<<(FF * 3 * H2 + 255) / 256, 256>>>(w3, w3h, w3l, FF, H2, H2);

    conv_mma<H1, CP1, false, true><<<dim3(H1 / 128, BB), 256, DYN_SMEM>>>(
        bufT, indexes, w1h, w1l, b1, nullptr, part, buf1);
    finalize_stats<<<(BB + 127) / 128, 128>>>(part, H1 / 128, st1, (float)(H1 * MM));

    conv_mma<H2, H1, true, true><<<dim3(H2 / 128, BB), 256, DYN_SMEM>>>(
        buf1, indexes, w2h, w2l, b2, st1, part, buf2);
    finalize_stats<<<(BB + 127) / 128, 128>>>(part, H2 / 128, st2, (float)(H2 * MM));

    conv_mma<FF, H2, true, false><<<dim3(FF / 128, BB), 256, DYN_SMEM>>>(
        buf2, indexes, w3h, w3l, b3, st2, nullptr, bufT);

    head_kernel<<<BB, 256>>>(bufT, gw1, gb1, gw2, gb2,
                             rw1, rb1, rw2, rb2, rw3, rb3, out,
                             write_comb, write_out);
}

// round 9
// speedup vs baseline: 6.8364x; 1.2574x over previous
#include <cuda_runtime.h>
#include <cuda_bf16.h>
#include <math.h>
#include <stdint.h>

// Shapes (fixed)
#define BB   512
#define MM   128
#define N3   381
#define CIN  200
#define CP1  256
#define H1   512
#define H2   512
#define FF   256

// Activations
__device__ __align__(16) float g_buf1[(size_t)BB * MM * H1];   // conv1 out / emb (reused)
__device__ __align__(16) float g_buf2[(size_t)BB * MM * H2];   // conv2 out
__device__ __align__(16) __nv_bfloat16 g_tHi[(size_t)BB * MM * CP1], g_tLo[(size_t)BB * MM * CP1];
__device__ __align__(16) __nv_bfloat16 g_aHi[(size_t)BB * MM * H1],  g_aLo[(size_t)BB * MM * H1];
// Weights, k' = k3*Cp + c order, bf16 hi/lo
__device__ __align__(16) __nv_bfloat16 g_w1_hi[H1 * 3 * CP1], g_w1_lo[H1 * 3 * CP1];
__device__ __align__(16) __nv_bfloat16 g_w2_hi[H2 * 3 * H1],  g_w2_lo[H2 * 3 * H1];
__device__ __align__(16) __nv_bfloat16 g_w3_hi[FF * 3 * H2],  g_w3_lo[FF * 3 * H2];
__device__ float2 g_part[BB * 4];
__device__ float2 g_stats1[BB];
__device__ float2 g_stats2[BB];

#define SW128(o) ((o) ^ (((o) >> 3) & 0x70))

__device__ __forceinline__ uint32_t smem_u32(const void* p) {
    uint32_t a;
    asm("{ .reg .u64 t; cvta.to.shared.u64 t, %1; cvt.u32.u64 %0, t; }" : "=r"(a) : "l"(p));
    return a;
}
__device__ __forceinline__ void ldmx4(uint32_t* r, uint32_t addr) {
    asm volatile("ldmatrix.sync.aligned.m8n8.x4.shared.b16 {%0,%1,%2,%3}, [%4];"
                 : "=r"(r[0]), "=r"(r[1]), "=r"(r[2]), "=r"(r[3]) : "r"(addr));
}
__device__ __forceinline__ void mma16816(float* c, const uint32_t* a, uint32_t b0, uint32_t b1) {
    asm volatile(
        "mma.sync.aligned.m16n8k16.row.col.f32.bf16.bf16.f32 "
        "{%0,%1,%2,%3},{%4,%5,%6,%7},{%8,%9},{%0,%1,%2,%3};"
        : "+f"(c[0]), "+f"(c[1]), "+f"(c[2]), "+f"(c[3])
        : "r"(a[0]), "r"(a[1]), "r"(a[2]), "r"(a[3]), "r"(b0), "r"(b1));
}
__device__ __forceinline__ void split_bf16(float x, unsigned short& h, unsigned short& l) {
    __nv_bfloat16 hh = __float2bfloat16_rn(x);
    h = __bfloat16_as_ushort(hh);
    l = __bfloat16_as_ushort(__float2bfloat16_rn(x - __bfloat162float(hh)));
}

// ---------------------------------------------------------------------------
// trees [B][CIN][128] -> hi/lo bf16 [B][128][CP1] (pad c>=CIN with 0)
// ---------------------------------------------------------------------------
__global__ __launch_bounds__(256) void transpose_split(
    const float* __restrict__ in,
    __nv_bfloat16* __restrict__ ohi, __nv_bfloat16* __restrict__ olo)
{
    __shared__ float tile[32][33];
    const int b = blockIdx.z;
    const int c0 = blockIdx.x * 32, m0 = blockIdx.y * 32;
    const int tx = threadIdx.x & 31, ty = threadIdx.x >> 5;
    const float* ib = in + (size_t)b * CIN * MM;
    #pragma unroll
    for (int i = 0; i < 4; i++) {
        int c = c0 + ty + i * 8;
        tile[ty + i * 8][tx] = (c < CIN) ? ib[c * MM + m0 + tx] : 0.f;
    }
    __syncthreads();
    #pragma unroll
    for (int i = 0; i < 4; i++) {
        int m = m0 + ty + i * 8;
        float v = tile[tx][ty + i * 8];
        unsigned short h, l;
        split_bf16(v, h, l);
        size_t o = (size_t)b * MM * CP1 + (size_t)m * CP1 + c0 + tx;
        ohi[o] = __ushort_as_bfloat16(h);
        olo[o] = __ushort_as_bfloat16(l);
    }
}

// ---------------------------------------------------------------------------
// W[o][c*3+k3] -> hi/lo bf16 at [o][k3*Cp + c], zero-pad c>=C
// ---------------------------------------------------------------------------
__global__ void wprep(const float* __restrict__ w, __nv_bfloat16* __restrict__ hi,
                      __nv_bfloat16* __restrict__ lo, int O, int C, int Cp)
{
    int i = blockIdx.x * 256 + threadIdx.x;
    int KT = 3 * Cp;
    if (i >= O * KT) return;
    int o = i / KT, kp = i - o * KT;
    int k3 = kp / Cp, c = kp - k3 * Cp;
    float v = (c < C) ? w[o * C * 3 + c * 3 + k3] : 0.f;
    unsigned short h, l;
    split_bf16(v, h, l);
    hi[i] = __ushort_as_bfloat16(h);
    lo[i] = __ushort_as_bfloat16(l);
}

// ---------------------------------------------------------------------------
// LN(+ReLU) + bf16 split: fp32 [B][128][H] -> hi/lo bf16, same layout
// ---------------------------------------------------------------------------
__global__ __launch_bounds__(512) void ln_split(
    const float* __restrict__ in, const float2* __restrict__ stats,
    __nv_bfloat16* __restrict__ ohi, __nv_bfloat16* __restrict__ olo, int per)
{
    const int b = blockIdx.x;
    const float2 st = stats[b];
    const float mean = st.x, inv = st.y;
    const float4* ip = (const float4*)(in + (size_t)b * per);
    uint2* hp = (uint2*)(ohi + (size_t)b * per);
    uint2* lp = (uint2*)(olo + (size_t)b * per);
    const int n4 = per / 4;
    for (int i = threadIdx.x; i < n4; i += 512) {
        float4 v = ip[i];
        float x0 = fmaxf((v.x - mean) * inv, 0.f);
        float x1 = fmaxf((v.y - mean) * inv, 0.f);
        float x2 = fmaxf((v.z - mean) * inv, 0.f);
        float x3 = fmaxf((v.w - mean) * inv, 0.f);
        unsigned short h0, l0, h1, l1, h2, l2, h3, l3;
        split_bf16(x0, h0, l0); split_bf16(x1, h1, l1);
        split_bf16(x2, h2, l2); split_bf16(x3, h3, l3);
        hp[i] = make_uint2((uint32_t)h0 | ((uint32_t)h1 << 16),
                           (uint32_t)h2 | ((uint32_t)h3 << 16));
        lp[i] = make_uint2((uint32_t)l0 | ((uint32_t)l1 << 16),
                           (uint32_t)l2 | ((uint32_t)l3 << 16));
    }
}

// ---------------------------------------------------------------------------
// Node-major warp-MMA conv, 512 threads (16 warps, 32x32 warp tiles),
// pure-copy staging (inputs pre-split bf16 hi/lo), 2-stage pipeline.
// ---------------------------------------------------------------------------
#define STG 65536
#define DYN_SMEM (2 * STG)

template<int O, int Cp, bool STATS>
__global__ __launch_bounds__(512, 1) void conv_mma(
    const __nv_bfloat16* __restrict__ Xhi,   // [B][128][Cp]
    const __nv_bfloat16* __restrict__ Xlo,
    const int*   __restrict__ idx,           // [B][381]
    const __nv_bfloat16* __restrict__ whi,   // [O][3*Cp]
    const __nv_bfloat16* __restrict__ wlo,
    const float* __restrict__ bias,
    float2* __restrict__ part_out,
    float* __restrict__ out)                 // [B][128][O]
{
    const int KT = 3 * Cp;
    const int NCH = Cp / 64;
    const int NC = 3 * NCH;

    extern __shared__ char base[];
    __shared__ int idxs[384];
    __shared__ float sbias[128];
    __shared__ float redS[16], redS2[16];

    const int b  = blockIdx.y;
    const int o0 = blockIdx.x * 128;
    const int t  = threadIdx.x;
    const int wid = t >> 5, lane = t & 31;

    for (int i = t; i < 384; i += 512) idxs[i] = (i < N3) ? idx[b * N3 + i] : 0;
    if (t < 128) sbias[t] = bias[o0 + t];
    __syncthreads();

    const __nv_bfloat16* XhB = Xhi + (size_t)b * MM * Cp;
    const __nv_bfloat16* XlB = Xlo + (size_t)b * MM * Cp;
    const uint32_t sbase = smem_u32(base);

    uint4 pfAh[2], pfAl[2], pfBh[2], pfBl[2];

    auto load_pf = [&](int ch) {
        const int k3 = ch / NCH, c0 = (ch - k3 * NCH) * 64;
        #pragma unroll
        for (int i = 0; i < 2; i++) {
            int e = i * 512 + t, r = e >> 3, part = e & 7;
            if (r < 127) {
                size_t g = (size_t)idxs[3 * r + k3] * Cp + c0 + part * 8;
                pfAh[i] = *(const uint4*)(XhB + g);
                pfAl[i] = *(const uint4*)(XlB + g);
            } else {
                pfAh[i] = make_uint4(0, 0, 0, 0);
                pfAl[i] = make_uint4(0, 0, 0, 0);
            }
            size_t gw = (size_t)(o0 + r) * KT + k3 * Cp + c0 + part * 8;
            pfBh[i] = *(const uint4*)(whi + gw);
            pfBl[i] = *(const uint4*)(wlo + gw);
        }
    };
    auto store_pf = [&](int s) {
        char* st = base + s * STG;
        #pragma unroll
        for (int i = 0; i < 2; i++) {
            int e = i * 512 + t, r = e >> 3, part = e & 7;
            uint32_t d = SW128(r * 128 + part * 16);
            *(uint4*)(st + 0     + d) = pfAh[i];
            *(uint4*)(st + 16384 + d) = pfAl[i];
            *(uint4*)(st + 32768 + d) = pfBh[i];
            *(uint4*)(st + 49152 + d) = pfBl[i];
        }
    };

    const int m0 = (wid & 3) * 32;
    const int n0 = (wid >> 2) * 32;

    float acc[2][4][4];
    #pragma unroll
    for (int i = 0; i < 2; i++)
        #pragma unroll
        for (int j = 0; j < 4; j++)
            #pragma unroll
            for (int q = 0; q < 4; q++) acc[i][j][q] = 0.f;

    load_pf(0);
    store_pf(0);
    __syncthreads();

    for (int ch = 0; ch < NC; ch++) {
        const int s = ch & 1;
        if (ch + 1 < NC) load_pf(ch + 1);

        const uint32_t tA_hi = sbase + s * STG;
        const uint32_t tA_lo = tA_hi + 16384;
        const uint32_t tB_hi = tA_hi + 32768;
        const uint32_t tB_lo = tA_hi + 49152;
        #pragma unroll
        for (int ks = 0; ks < 4; ks++) {
            uint32_t ah[2][4], al[2][4];
            const int arow = lane & 15, ahalf = lane >> 4;
            #pragma unroll
            for (int mi = 0; mi < 2; mi++) {
                uint32_t off = SW128((m0 + 16 * mi + arow) * 128 + ks * 32 + ahalf * 16);
                ldmx4(ah[mi], tA_hi + off);
                ldmx4(al[mi], tA_lo + off);
            }
            uint32_t bh[2][4], bl[2][4];
            #pragma unroll
            for (int h = 0; h < 2; h++) {
                uint32_t off = SW128((n0 + lane) * 128 + ks * 32 + h * 16);
                ldmx4(bh[h], tB_hi + off);
                ldmx4(bl[h], tB_lo + off);
            }
            #pragma unroll
            for (int mi = 0; mi < 2; mi++)
                #pragma unroll
                for (int nj = 0; nj < 4; nj++) {
                    mma16816(acc[mi][nj], ah[mi], bh[0][nj], bh[1][nj]);
                    mma16816(acc[mi][nj], ah[mi], bl[0][nj], bl[1][nj]);
                    mma16816(acc[mi][nj], al[mi], bh[0][nj], bh[1][nj]);
                }
        }
        if (ch + 1 < NC) store_pf(s ^ 1);
        __syncthreads();
    }

    // ---- epilogue: direct stores (m = r+1, row 0 zeroed) + register stats ----
    float* outB = out + (size_t)b * MM * O + o0;
    if (t < 128) outB[t] = 0.f;

    float s = 0.f, s2 = 0.f;
    #pragma unroll
    for (int mi = 0; mi < 2; mi++) {
        int r_lo = m0 + 16 * mi + (lane >> 2);
        int r_hi = r_lo + 8;
        #pragma unroll
        for (int nj = 0; nj < 4; nj++) {
            int n = n0 + 8 * nj + 2 * (lane & 3);
            float b0 = sbias[n], b1 = sbias[n + 1];
            float v0 = acc[mi][nj][0] + b0, v1 = acc[mi][nj][1] + b1;
            *(float2*)&outB[(size_t)(r_lo + 1) * O + n] = make_float2(v0, v1);
            if (STATS) { s += v0 + v1; s2 += v0 * v0 + v1 * v1; }
            if (r_hi < 127) {
                float v2 = acc[mi][nj][2] + b0, v3 = acc[mi][nj][3] + b1;
                *(float2*)&outB[(size_t)(r_hi + 1) * O + n] = make_float2(v2, v3);
                if (STATS) { s += v2 + v3; s2 += v2 * v2 + v3 * v3; }
            }
        }
    }
    if (STATS) {
        #pragma unroll
        for (int off = 16; off; off >>= 1) {
            s  += __shfl_xor_sync(0xFFFFFFFFu, s,  off);
            s2 += __shfl_xor_sync(0xFFFFFFFFu, s2, off);
        }
        if (lane == 0) { redS[wid] = s; redS2[wid] = s2; }
        __syncthreads();
        if (t == 0) {
            float S = 0.f, S2 = 0.f;
            #pragma unroll
            for (int i = 0; i < 16; i++) { S += redS[i]; S2 += redS2[i]; }
            part_out[b * (O / 128) + blockIdx.x] = make_float2(S, S2);
        }
    }
}

__global__ void finalize_stats(const float2* __restrict__ part, int nOC,
                               float2* __restrict__ stats, float cnt)
{
    int b = blockIdx.x * blockDim.x + threadIdx.x;
    if (b >= BB) return;
    float S = 0.f, S2 = 0.f;
    for (int i = 0; i < nOC; i++) { float2 p = part[b * nOC + i]; S += p.x; S2 += p.y; }
    double mean = (double)S / (double)cnt;
    double var  = ((double)S2 - (double)S * (double)S / (double)cnt) / ((double)cnt - 1.0);
    if (var < 0.0) var = 0.0;
    stats[b] = make_float2((float)mean, 1.f / ((float)sqrt(var) + 1e-5f));
}

// ---------------------------------------------------------------------------
// Attention head + MLP, emb node-major [B][128][256]
// ---------------------------------------------------------------------------
__global__ __launch_bounds__(256) void head_kernel(
    const float* __restrict__ emb,
    const float* __restrict__ gw1, const float* __restrict__ gb1,
    const float* __restrict__ gw2, const float* __restrict__ gb2,
    const float* __restrict__ rw1, const float* __restrict__ rb1,
    const float* __restrict__ rw2, const float* __restrict__ rb2,
    const float* __restrict__ rw3, const float* __restrict__ rb3,
    float* __restrict__ dout, int write_comb, int write_out)
{
    const int b = blockIdx.x;
    const int t = threadIdx.x;
    const float* E = emb + (size_t)b * MM * FF;

    __shared__ __align__(16) float es[128][33];
    __shared__ __align__(16) float gwT[32][132];
    __shared__ float gates[128];
    __shared__ float red[256];
    __shared__ float attn[128];
    __shared__ __align__(16) float comb[512];
    __shared__ float h1s[128];
    __shared__ float h2s[64];

    const int m  = t >> 1;
    const int h0 = (t & 1) * 64;

    float acc[64];
    #pragma unroll
    for (int j = 0; j < 64; j++) acc[j] = 0.f;

    for (int fc = 0; fc < FF; fc += 32) {
        #pragma unroll
        for (int i = 0; i < 16; i++) {
            int e = i * 256 + t;
            es[e >> 5][e & 31] = E[(e >> 5) * FF + fc + (e & 31)];
        }
        #pragma unroll
        for (int i = 0; i < 16; i++) {
            int e = i * 256 + t;
            gwT[e & 31][e >> 5] = gw1[(e >> 5) * FF + fc + (e & 31)];
        }
        __syncthreads();
        #pragma unroll 2
        for (int fl = 0; fl < 32; fl++) {
            float v = es[m][fl];
            const float* gr = &gwT[fl][h0];
            #pragma unroll
            for (int j = 0; j < 64; j++) acc[j] = fmaf(v, gr[j], acc[j]);
        }
        __syncthreads();
    }

    float g2 = 0.f;
    #pragma unroll
    for (int j = 0; j < 64; j++) {
        float g = acc[j] + gb1[h0 + j];
        g2 = fmaf(fmaxf(g, 0.f), gw2[h0 + j], g2);
    }
    red[t] = g2;
    __syncthreads();
    if ((t & 1) == 0) gates[m] = red[t] + red[t + 1] + gb2[0];
    __syncthreads();

    red[t] = (t < 128) ? gates[t] : -3.0e38f;
    __syncthreads();
    for (int off = 128; off > 0; off >>= 1) {
        if (t < off) red[t] = fmaxf(red[t], red[t + off]);
        __syncthreads();
    }
    float mx = red[0];
    __syncthreads();
    float ev = 0.f;
    if (t < 128) { ev = expf(gates[t] - mx); attn[t] = ev; }
    red[t] = (t < 128) ? ev : 0.f;
    __syncthreads();
    for (int off = 128; off > 0; off >>= 1) {
        if (t < off) red[t] += red[t + off];
        __syncthreads();
    }
    float sinv = 1.f / red[0];
    __syncthreads();
    if (t < 128) attn[t] *= sinv;
    __syncthreads();

    {
        const int f = t;
        float pf = 0.f;
        #pragma unroll 4
        for (int mi = 0; mi < 128; mi++)
            pf = fmaf(attn[mi], E[mi * FF + f], pf);
        comb[256 + f] = pf;
        comb[f]       = E[FF + f];
    }
    __syncthreads();

    if (write_comb) {
        dout[512 + (size_t)b * 512 + t]       = comb[t];
        dout[512 + (size_t)b * 512 + 256 + t] = comb[256 + t];
    }

    if (t < 128) {
        const float4* wr = (const float4*)(rw1 + t * 512);
        const float4* cb = (const float4*)comb;
        float a = rb1[t];
        #pragma unroll 8
        for (int q = 0; q < 128; q++) {
            float4 wv = wr[q];
            float4 cv = cb[q];
            a = fmaf(wv.x, cv.x, a);
            a = fmaf(wv.y, cv.y, a);
            a = fmaf(wv.z, cv.z, a);
            a = fmaf(wv.w, cv.w, a);
        }
        h1s[t] = fmaxf(a, 0.f);
    }
    __syncthreads();
    if (t < 64) {
        const float* wr = rw2 + t * 128;
        float a = rb2[t];
        #pragma unroll 4
        for (int i = 0; i < 128; i++) a = fmaf(h1s[i], wr[i], a);
        h2s[t] = fmaxf(a, 0.f);
    }
    __syncthreads();
    red[t] = (t < 64) ? h2s[t] * rw3[t] : 0.f;
    __syncthreads();
    for (int off = 32; off > 0; off >>= 1) {
        if (t < off) red[t] += red[t + off];
        __syncthreads();
    }
    if (t == 0 && write_out) dout[b] = red[0] + rb3[0];
}

// ---------------------------------------------------------------------------
extern "C" void kernel_launch(void* const* d_in, const int* in_sizes, int n_in,
                              void* d_out, int out_size)
{
    const float* trees   = (const float*)d_in[0];
    const int*   indexes = (const int*)  d_in[1];
    const float* w1  = (const float*)d_in[2];
    const float* b1  = (const float*)d_in[3];
    const float* w2  = (const float*)d_in[4];
    const float* b2  = (const float*)d_in[5];
    const float* w3  = (const float*)d_in[6];
    const float* b3  = (const float*)d_in[7];
    const float* gw1 = (const float*)d_in[8];
    const float* gb1 = (const float*)d_in[9];
    const float* gw2 = (const float*)d_in[10];
    const float* gb2 = (const float*)d_in[11];
    const float* rw1 = (const float*)d_in[12];
    const float* rb1 = (const float*)d_in[13];
    const float* rw2 = (const float*)d_in[14];
    const float* rb2 = (const float*)d_in[15];
    const float* rw3 = (const float*)d_in[16];
    const float* rb3 = (const float*)d_in[17];
    float* out = (float*)d_out;

    float *buf1, *buf2;
    __nv_bfloat16 *tHi, *tLo, *aHi, *aLo;
    __nv_bfloat16 *w1h, *w1l, *w2h, *w2l, *w3h, *w3l;
    float2 *part, *st1, *st2;
    cudaGetSymbolAddress((void**)&buf1, g_buf1);
    cudaGetSymbolAddress((void**)&buf2, g_buf2);
    cudaGetSymbolAddress((void**)&tHi, g_tHi);
    cudaGetSymbolAddress((void**)&tLo, g_tLo);
    cudaGetSymbolAddress((void**)&aHi, g_aHi);
    cudaGetSymbolAddress((void**)&aLo, g_aLo);
    cudaGetSymbolAddress((void**)&w1h, g_w1_hi);
    cudaGetSymbolAddress((void**)&w1l, g_w1_lo);
    cudaGetSymbolAddress((void**)&w2h, g_w2_hi);
    cudaGetSymbolAddress((void**)&w2l, g_w2_lo);
    cudaGetSymbolAddress((void**)&w3h, g_w3_hi);
    cudaGetSymbolAddress((void**)&w3l, g_w3_lo);
    cudaGetSymbolAddress((void**)&part, g_part);
    cudaGetSymbolAddress((void**)&st1, g_stats1);
    cudaGetSymbolAddress((void**)&st2, g_stats2);

    cudaFuncSetAttribute(conv_mma<H1, CP1, true>,
                         cudaFuncAttributeMaxDynamicSharedMemorySize, DYN_SMEM);
    cudaFuncSetAttribute(conv_mma<H2, H1, true>,
                         cudaFuncAttributeMaxDynamicSharedMemorySize, DYN_SMEM);
    cudaFuncSetAttribute(conv_mma<FF, H2, false>,
                         cudaFuncAttributeMaxDynamicSharedMemorySize, DYN_SMEM);

    const long long need_comb = 512LL + (long long)BB * 512LL;
    int write_comb = ((long long)out_size >= need_comb) ? 1 : 0;
    int write_out  = (out_size >= BB) ? 1 : 0;

    transpose_split<<<dim3(CP1 / 32, MM / 32, BB), 256>>>(trees, tHi, tLo);
    wprep<<<(H1 * 3 * CP1 + 255) / 256, 256>>>(w1, w1h, w1l, H1, CIN, CP1);
    wprep<<<(H2 * 3 * H1 + 255) / 256, 256>>>(w2, w2h, w2l, H2, H1, H1);
    wprep<<<(FF * 3 * H2 + 255) / 256, 256>>>(w3, w3h, w3l, FF, H2, H2);

    conv_mma<H1, CP1, true><<<dim3(H1 / 128, BB), 512, DYN_SMEM>>>(
        tHi, tLo, indexes, w1h, w1l, b1, part, buf1);
    finalize_stats<<<(BB + 127) / 128, 128>>>(part, H1 / 128, st1, (float)(H1 * MM));
    ln_split<<<BB, 512>>>(buf1, st1, aHi, aLo, MM * H1);

    conv_mma<H2, H1, true><<<dim3(H2 / 128, BB), 512, DYN_SMEM>>>(
        aHi, aLo, indexes, w2h, w2l, b2, part, buf2);
    finalize_stats<<<(BB + 127) / 128, 128>>>(part, H2 / 128, st2, (float)(H2 * MM));
    ln_split<<<BB, 512>>>(buf2, st2, aHi, aLo, MM * H2);

    conv_mma<FF, H2, false><<<dim3(FF / 128, BB), 512, DYN_SMEM>>>(
        aHi, aLo, indexes, w3h, w3l, b3, nullptr, buf1);

    head_kernel<<<BB, 256>>>(buf1, gw1, gb1, gw2, gb2,
                             rw1, rb1, rw2, rb2, rw3, rb3, out,
                             write_comb, write_out);
}